// round 1
// baseline (speedup 1.0000x reference)
#include <cuda_runtime.h>
#include <cstdint>
#include <math.h>

// Problem dims (fixed)
#define SEQ   1024
#define DH    64
#define HEADS 64          // bz*16
#define MD    1024        // model_dim
#define ND    2048        // model_dim * n_scale
#define MROWS 4096        // bz*seq

// Scratch (allocation-free rule: device globals)
__device__ float g_rp[(size_t)MROWS * ND];          // 32 MB: rp, then x = rp+out
__device__ float g_ctot[(size_t)HEADS * SEQ * 128]; // 32 MB: ctx1/ctx2 interleaved

// ---------------------------------------------------------------------------
// Tiled fp32 SGEMM, C[m,n] = sum_k A[m,k]*B[n,k] + bias[n] (+ addend[m,n])
// BM=BN=128, BK=8, 256 threads, 8x8 microtile. M,N %128==0, K %8==0 assumed.
// ---------------------------------------------------------------------------
__global__ void sgemm_nt(const float* __restrict__ A, const float* __restrict__ B,
                         const float* __restrict__ bias, const float* __restrict__ addend,
                         float* __restrict__ C, int M, int N, int K)
{
    __shared__ float As[8][128];
    __shared__ float Bs[8][128];
    const int tid = threadIdx.x;
    const int tx = tid & 15, ty = tid >> 4;
    const int m0 = blockIdx.y * 128, n0 = blockIdx.x * 128;

    float acc[8][8];
#pragma unroll
    for (int i = 0; i < 8; i++)
#pragma unroll
        for (int j = 0; j < 8; j++) acc[i][j] = 0.f;

    const int lr = tid >> 1;            // 0..127
    const int lc = (tid & 1) * 4;       // 0 or 4
    const float* Ap = A + (size_t)(m0 + lr) * K + lc;
    const float* Bp = B + (size_t)(n0 + lr) * K + lc;

    for (int k0 = 0; k0 < K; k0 += 8) {
        float4 a4 = *(const float4*)(Ap + k0);
        float4 b4 = *(const float4*)(Bp + k0);
        As[lc + 0][lr] = a4.x; As[lc + 1][lr] = a4.y;
        As[lc + 2][lr] = a4.z; As[lc + 3][lr] = a4.w;
        Bs[lc + 0][lr] = b4.x; Bs[lc + 1][lr] = b4.y;
        Bs[lc + 2][lr] = b4.z; Bs[lc + 3][lr] = b4.w;
        __syncthreads();
#pragma unroll
        for (int kk = 0; kk < 8; kk++) {
            float ar[8], br[8];
#pragma unroll
            for (int i = 0; i < 8; i++) ar[i] = As[kk][ty * 8 + i];
#pragma unroll
            for (int j = 0; j < 8; j++) br[j] = Bs[kk][tx * 8 + j];
#pragma unroll
            for (int i = 0; i < 8; i++)
#pragma unroll
                for (int j = 0; j < 8; j++)
                    acc[i][j] = fmaf(ar[i], br[j], acc[i][j]);
        }
        __syncthreads();
    }

#pragma unroll
    for (int i = 0; i < 8; i++) {
        const int m = m0 + ty * 8 + i;
#pragma unroll
        for (int j = 0; j < 8; j++) {
            const int n = n0 + tx * 8 + j;
            float v = acc[i][j] + bias[n];
            if (addend) v += addend[(size_t)m * N + n];
            C[(size_t)m * N + n] = v;
        }
    }
}

// ---------------------------------------------------------------------------
// Attention pass over one head slab: Q[1024,64] K[1024,64] V[1024,64].
// scores = (Q K^T) * 8 ; attn = softmax rows ; ctx = attn @ V.
// Block = (head, 64-row q tile), 256 threads (ty 0..15 -> 4 q rows each,
// tx 0..15 -> key/dim index tx+16j). Two-phase: stats, then recompute+emit.
// ctx written into g_ctot with row stride 128 at column offset ctx_off.
// ---------------------------------------------------------------------------
#define SROW 66  // smem row stride (pad vs 64 to kill bank conflicts)

__global__ void attn_pass(const float* __restrict__ Qbase, int q_head_stride, int q_row_stride,
                          const float* __restrict__ Kin, const float* __restrict__ Vin,
                          float* __restrict__ attn_out,   // nullptr for pass 2
                          float* __restrict__ ctx_out, int ctx_off)
{
    extern __shared__ float sm[];
    float* sQ = sm;
    float* sK = sm + 64 * SROW;
    float* sV = sm + 2 * 64 * SROW;
    float* sP = sm + 3 * 64 * SROW;

    const int H  = blockIdx.y;
    const int q0 = blockIdx.x * 64;
    const int tid = threadIdx.x;
    const int tx = tid & 15, ty = tid >> 4;

    const float* Qh = Qbase + (size_t)H * q_head_stride + (size_t)q0 * q_row_stride;
    const float* Kh = Kin + (size_t)H * (SEQ * DH);
    const float* Vh = Vin + (size_t)H * (SEQ * DH);

    // Load Q tile (64 x 64)
    {
        const int r  = tid >> 2;          // 0..63
        const int c0 = (tid & 3) * 16;    // 0,16,32,48
#pragma unroll
        for (int i = 0; i < 4; i++) {
            float4 val = *(const float4*)(Qh + (size_t)r * q_row_stride + c0 + i * 4);
            sQ[r * SROW + c0 + i * 4 + 0] = val.x;
            sQ[r * SROW + c0 + i * 4 + 1] = val.y;
            sQ[r * SROW + c0 + i * 4 + 2] = val.z;
            sQ[r * SROW + c0 + i * 4 + 3] = val.w;
        }
    }

    float mrow[4], lrow[4];
#pragma unroll
    for (int i = 0; i < 4; i++) { mrow[i] = -INFINITY; lrow[i] = 0.f; }

    __syncthreads();

    // ---------------- Phase 1: row max + sum(exp) ----------------
    for (int kb = 0; kb < 16; kb++) {
        const int r  = tid >> 2;
        const int c0 = (tid & 3) * 16;
#pragma unroll
        for (int i = 0; i < 4; i++) {
            float4 val = *(const float4*)(Kh + (size_t)(kb * 64 + r) * DH + c0 + i * 4);
            sK[r * SROW + c0 + i * 4 + 0] = val.x;
            sK[r * SROW + c0 + i * 4 + 1] = val.y;
            sK[r * SROW + c0 + i * 4 + 2] = val.z;
            sK[r * SROW + c0 + i * 4 + 3] = val.w;
        }
        __syncthreads();

        float s[4][4];
#pragma unroll
        for (int a = 0; a < 4; a++)
#pragma unroll
            for (int b = 0; b < 4; b++) s[a][b] = 0.f;

#pragma unroll 8
        for (int d = 0; d < 64; d += 2) {
            float2 qa[4], ka[4];
#pragma unroll
            for (int a = 0; a < 4; a++) qa[a] = *(const float2*)&sQ[(ty * 4 + a) * SROW + d];
#pragma unroll
            for (int b = 0; b < 4; b++) ka[b] = *(const float2*)&sK[(tx + 16 * b) * SROW + d];
#pragma unroll
            for (int a = 0; a < 4; a++)
#pragma unroll
                for (int b = 0; b < 4; b++)
                    s[a][b] = fmaf(qa[a].x, ka[b].x, fmaf(qa[a].y, ka[b].y, s[a][b]));
        }

#pragma unroll
        for (int a = 0; a < 4; a++) {
#pragma unroll
            for (int b = 0; b < 4; b++) s[a][b] *= 8.f;  // scale = sqrt(d_head)
            float mx = fmaxf(fmaxf(s[a][0], s[a][1]), fmaxf(s[a][2], s[a][3]));
#pragma unroll
            for (int off = 8; off; off >>= 1)
                mx = fmaxf(mx, __shfl_xor_sync(0xffffffffu, mx, off));
            const float nm = fmaxf(mrow[a], mx);
            float se = 0.f;
#pragma unroll
            for (int b = 0; b < 4; b++) se += __expf(s[a][b] - nm);
#pragma unroll
            for (int off = 8; off; off >>= 1)
                se += __shfl_xor_sync(0xffffffffu, se, off);
            lrow[a] = lrow[a] * __expf(mrow[a] - nm) + se;
            mrow[a] = nm;
        }
        __syncthreads();
    }

    float invl[4];
#pragma unroll
    for (int a = 0; a < 4; a++) invl[a] = 1.f / lrow[a];

    float ctx[4][4];
#pragma unroll
    for (int a = 0; a < 4; a++)
#pragma unroll
        for (int b = 0; b < 4; b++) ctx[a][b] = 0.f;

    // ---------------- Phase 2: probabilities + ctx ----------------
    for (int kb = 0; kb < 16; kb++) {
        const int r  = tid >> 2;
        const int c0 = (tid & 3) * 16;
#pragma unroll
        for (int i = 0; i < 4; i++) {
            float4 kv = *(const float4*)(Kh + (size_t)(kb * 64 + r) * DH + c0 + i * 4);
            sK[r * SROW + c0 + i * 4 + 0] = kv.x;
            sK[r * SROW + c0 + i * 4 + 1] = kv.y;
            sK[r * SROW + c0 + i * 4 + 2] = kv.z;
            sK[r * SROW + c0 + i * 4 + 3] = kv.w;
            float4 vv = *(const float4*)(Vh + (size_t)(kb * 64 + r) * DH + c0 + i * 4);
            sV[r * SROW + c0 + i * 4 + 0] = vv.x;
            sV[r * SROW + c0 + i * 4 + 1] = vv.y;
            sV[r * SROW + c0 + i * 4 + 2] = vv.z;
            sV[r * SROW + c0 + i * 4 + 3] = vv.w;
        }
        __syncthreads();

        float s[4][4];
#pragma unroll
        for (int a = 0; a < 4; a++)
#pragma unroll
            for (int b = 0; b < 4; b++) s[a][b] = 0.f;

#pragma unroll 8
        for (int d = 0; d < 64; d += 2) {
            float2 qa[4], ka[4];
#pragma unroll
            for (int a = 0; a < 4; a++) qa[a] = *(const float2*)&sQ[(ty * 4 + a) * SROW + d];
#pragma unroll
            for (int b = 0; b < 4; b++) ka[b] = *(const float2*)&sK[(tx + 16 * b) * SROW + d];
#pragma unroll
            for (int a = 0; a < 4; a++)
#pragma unroll
                for (int b = 0; b < 4; b++)
                    s[a][b] = fmaf(qa[a].x, ka[b].x, fmaf(qa[a].y, ka[b].y, s[a][b]));
        }

#pragma unroll
        for (int a = 0; a < 4; a++) {
#pragma unroll
            for (int b = 0; b < 4; b++) {
                const float p = __expf(s[a][b] * 8.f - mrow[a]) * invl[a];
                sP[(ty * 4 + a) * SROW + tx + 16 * b] = p;
                if (attn_out)
                    attn_out[((size_t)H * SEQ + q0 + ty * 4 + a) * SEQ + kb * 64 + tx + 16 * b] = p;
            }
        }
        __syncthreads();

#pragma unroll 8
        for (int kk = 0; kk < 64; kk += 2) {
            float2 pv[4];
#pragma unroll
            for (int a = 0; a < 4; a++) pv[a] = *(const float2*)&sP[(ty * 4 + a) * SROW + kk];
            float v0[4], v1[4];
#pragma unroll
            for (int b = 0; b < 4; b++) {
                v0[b] = sV[kk * SROW + tx + 16 * b];
                v1[b] = sV[(kk + 1) * SROW + tx + 16 * b];
            }
#pragma unroll
            for (int a = 0; a < 4; a++)
#pragma unroll
                for (int b = 0; b < 4; b++)
                    ctx[a][b] = fmaf(pv[a].x, v0[b], fmaf(pv[a].y, v1[b], ctx[a][b]));
        }
        __syncthreads();
    }

    // Write ctx into interleaved ctot: row stride 128, columns ctx_off + d
#pragma unroll
    for (int a = 0; a < 4; a++)
#pragma unroll
        for (int b = 0; b < 4; b++)
            ctx_out[((size_t)H * SEQ + q0 + ty * 4 + a) * 128 + ctx_off + tx + 16 * b] = ctx[a][b];
}

// ---------------------------------------------------------------------------
// Row LayerNorm over ND=2048: y = (x-mu)*rsqrt(var+eps)*gamma + beta
// ---------------------------------------------------------------------------
__global__ void ln_kernel(const float* __restrict__ X, const float* __restrict__ gamma,
                          const float* __restrict__ beta, float* __restrict__ Y)
{
    __shared__ float red[64];
    const int row = blockIdx.x;
    const float* x = X + (size_t)row * ND;
    float sum = 0.f, sq = 0.f;
    for (int i = threadIdx.x; i < ND; i += blockDim.x) {
        const float v = x[i];
        sum += v; sq += v * v;
    }
#pragma unroll
    for (int off = 16; off; off >>= 1) {
        sum += __shfl_xor_sync(0xffffffffu, sum, off);
        sq  += __shfl_xor_sync(0xffffffffu, sq, off);
    }
    const int warp = threadIdx.x >> 5, lane = threadIdx.x & 31;
    if (lane == 0) { red[warp] = sum; red[warp + 32] = sq; }
    __syncthreads();
    if (warp == 0) {
        sum = (lane < 8) ? red[lane] : 0.f;
        sq  = (lane < 8) ? red[lane + 32] : 0.f;
#pragma unroll
        for (int off = 4; off; off >>= 1) {
            sum += __shfl_xor_sync(0xffffffffu, sum, off);
            sq  += __shfl_xor_sync(0xffffffffu, sq, off);
        }
        if (lane == 0) { red[0] = sum; red[1] = sq; }
    }
    __syncthreads();
    const float mu  = red[0] * (1.f / ND);
    const float var = red[1] * (1.f / ND) - mu * mu;
    const float inv = rsqrtf(var + 1e-5f);
    float* y = Y + (size_t)row * ND;
    for (int i = threadIdx.x; i < ND; i += blockDim.x)
        y[i] = (x[i] - mu) * inv * gamma[i] + beta[i];
}

// ---------------------------------------------------------------------------
extern "C" void kernel_launch(void* const* d_in, const int* in_sizes, int n_in,
                              void* d_out, int out_size)
{
    const float* k_in  = (const float*)d_in[0];
    const float* v_in  = (const float*)d_in[1];
    const float* q_in  = (const float*)d_in[2];
    const float* r_in  = (const float*)d_in[3];
    const float* Wr    = (const float*)d_in[4];
    const float* br    = (const float*)d_in[5];
    const float* Wf    = (const float*)d_in[6];
    const float* bf    = (const float*)d_in[7];
    const float* gamma = (const float*)d_in[8];
    const float* beta  = (const float*)d_in[9];

    float* out      = (float*)d_out;
    float* y_out    = out;                              // [4,1024,2048]
    float* attn_out = out + (size_t)MROWS * ND;         // [64,1024,1024]

    float* rp;   cudaGetSymbolAddress((void**)&rp, g_rp);
    float* ctot; cudaGetSymbolAddress((void**)&ctot, g_ctot);

    const int attn_smem = 4 * 64 * SROW * (int)sizeof(float);  // 67584 B
    cudaFuncSetAttribute(attn_pass, cudaFuncAttributeMaxDynamicSharedMemorySize, attn_smem);

    // 1) rp = r @ Wr^T + br
    dim3 g1(ND / 128, MROWS / 128);
    sgemm_nt<<<g1, 256>>>(r_in, Wr, br, nullptr, rp, MROWS, ND, MD);

    // 2) pass 1: attn1 -> d_out, ctx1 -> ctot[..,0:64]
    dim3 ga(SEQ / 64, HEADS);
    attn_pass<<<ga, 256, attn_smem>>>(q_in, SEQ * DH, DH, k_in, v_in, attn_out, ctot, 0);

    // 3) pass 2: queries = ctx1 (ctot stride 128), ctx2 -> ctot[..,64:128]
    attn_pass<<<ga, 256, attn_smem>>>(ctot, SEQ * 128, 128, k_in, v_in, nullptr, ctot, 64);

    // 4) x = ctot @ Wf^T + bf + rp   (in place into rp)
    sgemm_nt<<<g1, 256>>>(ctot, Wf, bf, rp, rp, MROWS, ND, ND);

    // 5) y = LayerNorm(x) * gamma + beta
    ln_kernel<<<MROWS, 256>>>(rp, gamma, beta, y_out);
}

// round 2
// speedup vs baseline: 1.6008x; 1.6008x over previous
#include <cuda_runtime.h>
#include <cstdint>
#include <math.h>

// Problem dims (fixed)
#define SEQ   1024
#define DH    64
#define HEADS 64          // bz*16
#define MD    1024        // model_dim
#define ND    2048        // model_dim * n_scale
#define MROWS 4096        // bz*seq

// Scratch (allocation-free rule: device globals)
__device__ float g_rp[(size_t)MROWS * ND];            // 32 MB: rp, then x = rp+out
__device__ float g_ctot[(size_t)HEADS * SEQ * 128];   // 32 MB: ctx1/ctx2 interleaved
__device__ float g_scores[(size_t)HEADS * SEQ * SEQ]; // 256 MB: raw scaled scores cache

// ---------------------------------------------------------------------------
// TF32 tensor-core GEMM: C[m,n] = sum_k A[m,k]*B[n,k] + bias[n] (+ addend)
// BM=BN=128, BK=16, 256 threads = 8 warps (4x2), warp tile 32x64,
// mma.sync.m16n8k8.tf32. M,N %128==0, K %16==0 assumed.
// ---------------------------------------------------------------------------
#define GSTR 20   // smem row stride in words (pad 16 -> 20: conflict-free frags)

__device__ __forceinline__ uint32_t f2tf32(float x) {
    uint32_t r;
    asm("cvt.rna.tf32.f32 %0, %1;" : "=r"(r) : "f"(x));
    return r;
}

__device__ __forceinline__ void mma_tf32(float* c, const uint32_t* a, const uint32_t* b) {
    asm volatile(
        "mma.sync.aligned.m16n8k8.row.col.f32.tf32.tf32.f32 "
        "{%0,%1,%2,%3},{%4,%5,%6,%7},{%8,%9},{%0,%1,%2,%3};"
        : "+f"(c[0]), "+f"(c[1]), "+f"(c[2]), "+f"(c[3])
        : "r"(a[0]), "r"(a[1]), "r"(a[2]), "r"(a[3]), "r"(b[0]), "r"(b[1]));
}

__global__ void gemm_tf32(const float* __restrict__ A, const float* __restrict__ B,
                          const float* __restrict__ bias, const float* __restrict__ addend,
                          float* __restrict__ C, int M, int N, int K)
{
    __shared__ uint32_t As[128 * GSTR];
    __shared__ uint32_t Bs[128 * GSTR];

    const int tid  = threadIdx.x;
    const int warp = tid >> 5, lane = tid & 31;
    const int wm = (warp >> 1) * 32;   // 0,32,64,96
    const int wn = (warp & 1) * 64;    // 0,64
    const int m0 = blockIdx.y * 128, n0 = blockIdx.x * 128;
    const int g  = lane >> 2;          // groupID 0..7
    const int tg = lane & 3;           // thread-in-group 0..3

    float acc[2][8][4];
#pragma unroll
    for (int i = 0; i < 2; i++)
#pragma unroll
        for (int j = 0; j < 8; j++)
#pragma unroll
            for (int r = 0; r < 4; r++) acc[i][j][r] = 0.f;

    const int lrow  = tid >> 2;          // 0..63
    const int lquad = (tid & 3) * 4;     // 0,4,8,12
    const float* Ap = A + (size_t)(m0 + lrow) * K + lquad;
    const float* Bp = B + (size_t)(n0 + lrow) * K + lquad;

    for (int k0 = 0; k0 < K; k0 += 16) {
        float4 a0 = *(const float4*)(Ap + k0);
        float4 a1 = *(const float4*)(Ap + (size_t)64 * K + k0);
        float4 b0 = *(const float4*)(Bp + k0);
        float4 b1 = *(const float4*)(Bp + (size_t)64 * K + k0);
        uint32_t* as0 = &As[lrow * GSTR + lquad];
        uint32_t* as1 = &As[(lrow + 64) * GSTR + lquad];
        uint32_t* bs0 = &Bs[lrow * GSTR + lquad];
        uint32_t* bs1 = &Bs[(lrow + 64) * GSTR + lquad];
        as0[0] = f2tf32(a0.x); as0[1] = f2tf32(a0.y); as0[2] = f2tf32(a0.z); as0[3] = f2tf32(a0.w);
        as1[0] = f2tf32(a1.x); as1[1] = f2tf32(a1.y); as1[2] = f2tf32(a1.z); as1[3] = f2tf32(a1.w);
        bs0[0] = f2tf32(b0.x); bs0[1] = f2tf32(b0.y); bs0[2] = f2tf32(b0.z); bs0[3] = f2tf32(b0.w);
        bs1[0] = f2tf32(b1.x); bs1[1] = f2tf32(b1.y); bs1[2] = f2tf32(b1.z); bs1[3] = f2tf32(b1.w);
        __syncthreads();

#pragma unroll
        for (int ks = 0; ks < 16; ks += 8) {
            uint32_t afrag[2][4], bfrag[8][2];
#pragma unroll
            for (int mi = 0; mi < 2; mi++) {
                const int row = wm + mi * 16 + g;
                afrag[mi][0] = As[row * GSTR + ks + tg];
                afrag[mi][1] = As[(row + 8) * GSTR + ks + tg];
                afrag[mi][2] = As[row * GSTR + ks + tg + 4];
                afrag[mi][3] = As[(row + 8) * GSTR + ks + tg + 4];
            }
#pragma unroll
            for (int ni = 0; ni < 8; ni++) {
                const int col = wn + ni * 8 + g;
                bfrag[ni][0] = Bs[col * GSTR + ks + tg];
                bfrag[ni][1] = Bs[col * GSTR + ks + tg + 4];
            }
#pragma unroll
            for (int mi = 0; mi < 2; mi++)
#pragma unroll
                for (int ni = 0; ni < 8; ni++)
                    mma_tf32(acc[mi][ni], afrag[mi], bfrag[ni]);
        }
        __syncthreads();
    }

#pragma unroll
    for (int mi = 0; mi < 2; mi++) {
#pragma unroll
        for (int ni = 0; ni < 8; ni++) {
            const int m = m0 + wm + mi * 16 + g;
            const int n = n0 + wn + ni * 8 + tg * 2;
            const float bx = bias[n], by = bias[n + 1];
            float2 v0 = make_float2(acc[mi][ni][0] + bx, acc[mi][ni][1] + by);
            float2 v1 = make_float2(acc[mi][ni][2] + bx, acc[mi][ni][3] + by);
            if (addend) {
                float2 d0 = *(const float2*)(addend + (size_t)m * N + n);
                float2 d1 = *(const float2*)(addend + (size_t)(m + 8) * N + n);
                v0.x += d0.x; v0.y += d0.y; v1.x += d1.x; v1.y += d1.y;
            }
            *(float2*)(C + (size_t)m * N + n) = v0;
            *(float2*)(C + (size_t)(m + 8) * N + n) = v1;
        }
    }
}

// ---------------------------------------------------------------------------
// Attention pass: Q[1024,64] K[1024,64] V[1024,64] per head.
// scores = (Q K^T) * 8 ; attn = softmax rows ; ctx = attn @ V.
// Phase 1 computes scores ONCE, caches them (scaled) in g_scores, and builds
// running max/sum. Phase 2 reads cached scores, normalizes, emits attn + ctx.
// ctx written into g_ctot (row stride 128) at column offset ctx_off.
// ---------------------------------------------------------------------------
#define SROW 66  // smem row stride (pad vs 64 to kill bank conflicts)

__global__ void attn_pass(const float* __restrict__ Qbase, int q_head_stride, int q_row_stride,
                          const float* __restrict__ Kin, const float* __restrict__ Vin,
                          float* __restrict__ scores,     // [HEADS][SEQ][SEQ] scratch
                          float* __restrict__ attn_out,   // nullptr for pass 2
                          float* __restrict__ ctx_out, int ctx_off)
{
    extern __shared__ float sm[];
    float* sQ = sm;
    float* sK = sm + 64 * SROW;
    float* sV = sm + 2 * 64 * SROW;
    float* sP = sm + 3 * 64 * SROW;

    const int H  = blockIdx.y;
    const int q0 = blockIdx.x * 64;
    const int tid = threadIdx.x;
    const int tx = tid & 15, ty = tid >> 4;

    const float* Qh = Qbase + (size_t)H * q_head_stride + (size_t)q0 * q_row_stride;
    const float* Kh = Kin + (size_t)H * (SEQ * DH);
    const float* Vh = Vin + (size_t)H * (SEQ * DH);
    float* Sh = scores + (size_t)H * SEQ * SEQ + (size_t)q0 * SEQ;

    // Load Q tile (64 x 64)
    {
        const int r  = tid >> 2;
        const int c0 = (tid & 3) * 16;
#pragma unroll
        for (int i = 0; i < 4; i++) {
            float4 val = *(const float4*)(Qh + (size_t)r * q_row_stride + c0 + i * 4);
            sQ[r * SROW + c0 + i * 4 + 0] = val.x;
            sQ[r * SROW + c0 + i * 4 + 1] = val.y;
            sQ[r * SROW + c0 + i * 4 + 2] = val.z;
            sQ[r * SROW + c0 + i * 4 + 3] = val.w;
        }
    }

    float mrow[4], lrow[4];
#pragma unroll
    for (int i = 0; i < 4; i++) { mrow[i] = -INFINITY; lrow[i] = 0.f; }

    __syncthreads();

    // ---------------- Phase 1: scores -> cache, row max + sum(exp) ----------
    for (int kb = 0; kb < 16; kb++) {
        const int r  = tid >> 2;
        const int c0 = (tid & 3) * 16;
#pragma unroll
        for (int i = 0; i < 4; i++) {
            float4 val = *(const float4*)(Kh + (size_t)(kb * 64 + r) * DH + c0 + i * 4);
            sK[r * SROW + c0 + i * 4 + 0] = val.x;
            sK[r * SROW + c0 + i * 4 + 1] = val.y;
            sK[r * SROW + c0 + i * 4 + 2] = val.z;
            sK[r * SROW + c0 + i * 4 + 3] = val.w;
        }
        __syncthreads();

        float s[4][4];
#pragma unroll
        for (int a = 0; a < 4; a++)
#pragma unroll
            for (int b = 0; b < 4; b++) s[a][b] = 0.f;

#pragma unroll 8
        for (int d = 0; d < 64; d += 2) {
            float2 qa[4], ka[4];
#pragma unroll
            for (int a = 0; a < 4; a++) qa[a] = *(const float2*)&sQ[(ty * 4 + a) * SROW + d];
#pragma unroll
            for (int b = 0; b < 4; b++) ka[b] = *(const float2*)&sK[(tx + 16 * b) * SROW + d];
#pragma unroll
            for (int a = 0; a < 4; a++)
#pragma unroll
                for (int b = 0; b < 4; b++)
                    s[a][b] = fmaf(qa[a].x, ka[b].x, fmaf(qa[a].y, ka[b].y, s[a][b]));
        }

#pragma unroll
        for (int a = 0; a < 4; a++) {
#pragma unroll
            for (int b = 0; b < 4; b++) {
                s[a][b] *= 8.f;  // scale = sqrt(d_head)
                Sh[(size_t)(ty * 4 + a) * SEQ + kb * 64 + tx + 16 * b] = s[a][b];
            }
            float mx = fmaxf(fmaxf(s[a][0], s[a][1]), fmaxf(s[a][2], s[a][3]));
#pragma unroll
            for (int off = 8; off; off >>= 1)
                mx = fmaxf(mx, __shfl_xor_sync(0xffffffffu, mx, off));
            const float nm = fmaxf(mrow[a], mx);
            float se = 0.f;
#pragma unroll
            for (int b = 0; b < 4; b++) se += __expf(s[a][b] - nm);
#pragma unroll
            for (int off = 8; off; off >>= 1)
                se += __shfl_xor_sync(0xffffffffu, se, off);
            lrow[a] = lrow[a] * __expf(mrow[a] - nm) + se;
            mrow[a] = nm;
        }
        __syncthreads();
    }

    float invl[4];
#pragma unroll
    for (int a = 0; a < 4; a++) invl[a] = 1.f / lrow[a];

    float ctx[4][4];
#pragma unroll
    for (int a = 0; a < 4; a++)
#pragma unroll
        for (int b = 0; b < 4; b++) ctx[a][b] = 0.f;

    // ---------------- Phase 2: normalize cached scores + ctx ----------------
    for (int kb = 0; kb < 16; kb++) {
        const int r  = tid >> 2;
        const int c0 = (tid & 3) * 16;
#pragma unroll
        for (int i = 0; i < 4; i++) {
            float4 vv = *(const float4*)(Vh + (size_t)(kb * 64 + r) * DH + c0 + i * 4);
            sV[r * SROW + c0 + i * 4 + 0] = vv.x;
            sV[r * SROW + c0 + i * 4 + 1] = vv.y;
            sV[r * SROW + c0 + i * 4 + 2] = vv.z;
            sV[r * SROW + c0 + i * 4 + 3] = vv.w;
        }

#pragma unroll
        for (int a = 0; a < 4; a++) {
#pragma unroll
            for (int b = 0; b < 4; b++) {
                const float sc = Sh[(size_t)(ty * 4 + a) * SEQ + kb * 64 + tx + 16 * b];
                const float p = __expf(sc - mrow[a]) * invl[a];
                sP[(ty * 4 + a) * SROW + tx + 16 * b] = p;
                if (attn_out)
                    attn_out[((size_t)H * SEQ + q0 + ty * 4 + a) * SEQ + kb * 64 + tx + 16 * b] = p;
            }
        }
        __syncthreads();

#pragma unroll 8
        for (int kk = 0; kk < 64; kk += 2) {
            float2 pv[4];
#pragma unroll
            for (int a = 0; a < 4; a++) pv[a] = *(const float2*)&sP[(ty * 4 + a) * SROW + kk];
            float v0[4], v1[4];
#pragma unroll
            for (int b = 0; b < 4; b++) {
                v0[b] = sV[kk * SROW + tx + 16 * b];
                v1[b] = sV[(kk + 1) * SROW + tx + 16 * b];
            }
#pragma unroll
            for (int a = 0; a < 4; a++)
#pragma unroll
                for (int b = 0; b < 4; b++)
                    ctx[a][b] = fmaf(pv[a].x, v0[b], fmaf(pv[a].y, v1[b], ctx[a][b]));
        }
        __syncthreads();
    }

    // Write ctx into interleaved ctot: row stride 128, columns ctx_off + d
#pragma unroll
    for (int a = 0; a < 4; a++)
#pragma unroll
        for (int b = 0; b < 4; b++)
            ctx_out[((size_t)H * SEQ + q0 + ty * 4 + a) * 128 + ctx_off + tx + 16 * b] = ctx[a][b];
}

// ---------------------------------------------------------------------------
// Row LayerNorm over ND=2048
// ---------------------------------------------------------------------------
__global__ void ln_kernel(const float* __restrict__ X, const float* __restrict__ gamma,
                          const float* __restrict__ beta, float* __restrict__ Y)
{
    __shared__ float red[64];
    const int row = blockIdx.x;
    const float* x = X + (size_t)row * ND;
    float sum = 0.f, sq = 0.f;
    for (int i = threadIdx.x; i < ND; i += blockDim.x) {
        const float v = x[i];
        sum += v; sq += v * v;
    }
#pragma unroll
    for (int off = 16; off; off >>= 1) {
        sum += __shfl_xor_sync(0xffffffffu, sum, off);
        sq  += __shfl_xor_sync(0xffffffffu, sq, off);
    }
    const int warp = threadIdx.x >> 5, lane = threadIdx.x & 31;
    if (lane == 0) { red[warp] = sum; red[warp + 32] = sq; }
    __syncthreads();
    if (warp == 0) {
        sum = (lane < 8) ? red[lane] : 0.f;
        sq  = (lane < 8) ? red[lane + 32] : 0.f;
#pragma unroll
        for (int off = 4; off; off >>= 1) {
            sum += __shfl_xor_sync(0xffffffffu, sum, off);
            sq  += __shfl_xor_sync(0xffffffffu, sq, off);
        }
        if (lane == 0) { red[0] = sum; red[1] = sq; }
    }
    __syncthreads();
    const float mu  = red[0] * (1.f / ND);
    const float var = red[1] * (1.f / ND) - mu * mu;
    const float inv = rsqrtf(var + 1e-5f);
    float* y = Y + (size_t)row * ND;
    for (int i = threadIdx.x; i < ND; i += blockDim.x)
        y[i] = (x[i] - mu) * inv * gamma[i] + beta[i];
}

// ---------------------------------------------------------------------------
extern "C" void kernel_launch(void* const* d_in, const int* in_sizes, int n_in,
                              void* d_out, int out_size)
{
    const float* k_in  = (const float*)d_in[0];
    const float* v_in  = (const float*)d_in[1];
    const float* q_in  = (const float*)d_in[2];
    const float* r_in  = (const float*)d_in[3];
    const float* Wr    = (const float*)d_in[4];
    const float* br    = (const float*)d_in[5];
    const float* Wf    = (const float*)d_in[6];
    const float* bf    = (const float*)d_in[7];
    const float* gamma = (const float*)d_in[8];
    const float* beta  = (const float*)d_in[9];

    float* out      = (float*)d_out;
    float* y_out    = out;                              // [4,1024,2048]
    float* attn_out = out + (size_t)MROWS * ND;         // [64,1024,1024]

    float* rp;     cudaGetSymbolAddress((void**)&rp, g_rp);
    float* ctot;   cudaGetSymbolAddress((void**)&ctot, g_ctot);
    float* scores; cudaGetSymbolAddress((void**)&scores, g_scores);

    const int attn_smem = 4 * 64 * SROW * (int)sizeof(float);  // 67584 B
    cudaFuncSetAttribute(attn_pass, cudaFuncAttributeMaxDynamicSharedMemorySize, attn_smem);

    // 1) rp = r @ Wr^T + br   (TF32 tensor cores)
    dim3 g1(ND / 128, MROWS / 128);
    gemm_tf32<<<g1, 256>>>(r_in, Wr, br, nullptr, rp, MROWS, ND, MD);

    // 2) pass 1: attn1 -> d_out, ctx1 -> ctot[..,0:64]
    dim3 ga(SEQ / 64, HEADS);
    attn_pass<<<ga, 256, attn_smem>>>(q_in, SEQ * DH, DH, k_in, v_in, scores, attn_out, ctot, 0);

    // 3) pass 2: queries = ctx1 (ctot stride 128), ctx2 -> ctot[..,64:128]
    attn_pass<<<ga, 256, attn_smem>>>(ctot, SEQ * 128, 128, k_in, v_in, scores, nullptr, ctot, 64);

    // 4) x = ctot @ Wf^T + bf + rp   (TF32 tensor cores, in place into rp)
    gemm_tf32<<<g1, 256>>>(ctot, Wf, bf, rp, rp, MROWS, ND, ND);

    // 5) y = LayerNorm(x) * gamma + beta
    ln_kernel<<<MROWS, 256>>>(rp, gamma, beta, y_out);
}

// round 4
// speedup vs baseline: 1.7464x; 1.0910x over previous
#include <cuda_runtime.h>
#include <cstdint>
#include <math.h>

// Problem dims (fixed)
#define SEQ   1024
#define DH    64
#define HEADS 64          // bz*16
#define MD    1024        // model_dim
#define ND    2048        // model_dim * n_scale
#define MROWS 4096        // bz*seq

// Scratch (allocation-free rule: device globals)
__device__ float g_rp[(size_t)MROWS * ND];            // 32 MB
__device__ float g_ctot[(size_t)HEADS * SEQ * 128];   // 32 MB: ctx1/ctx2 interleaved
__device__ float g_scores[(size_t)HEADS * SEQ * SEQ]; // 256 MB: raw scaled scores

// ---------------------------------------------------------------------------
// TF32 tensor-core GEMM with register prefetch: C = A B^T + bias (+ addend)
// BM=BN=128, BK=16, 256 threads, warp tile 32x64, mma.m16n8k8.tf32.
// ---------------------------------------------------------------------------
#define GSTR 20

__device__ __forceinline__ uint32_t f2tf32(float x) {
    uint32_t r;
    asm("cvt.rna.tf32.f32 %0, %1;" : "=r"(r) : "f"(x));
    return r;
}

__device__ __forceinline__ void mma_tf32(float* c, const uint32_t* a, const uint32_t* b) {
    asm volatile(
        "mma.sync.aligned.m16n8k8.row.col.f32.tf32.tf32.f32 "
        "{%0,%1,%2,%3},{%4,%5,%6,%7},{%8,%9},{%0,%1,%2,%3};"
        : "+f"(c[0]), "+f"(c[1]), "+f"(c[2]), "+f"(c[3])
        : "r"(a[0]), "r"(a[1]), "r"(a[2]), "r"(a[3]), "r"(b[0]), "r"(b[1]));
}

__global__ void gemm_tf32(const float* __restrict__ A, const float* __restrict__ B,
                          const float* __restrict__ bias, const float* __restrict__ addend,
                          float* __restrict__ C, int M, int N, int K)
{
    __shared__ uint32_t As[128 * GSTR];
    __shared__ uint32_t Bs[128 * GSTR];

    const int tid  = threadIdx.x;
    const int warp = tid >> 5, lane = tid & 31;
    const int wm = (warp >> 1) * 32;
    const int wn = (warp & 1) * 64;
    const int m0 = blockIdx.y * 128, n0 = blockIdx.x * 128;
    const int g  = lane >> 2;
    const int tg = lane & 3;

    float acc[2][8][4];
#pragma unroll
    for (int i = 0; i < 2; i++)
#pragma unroll
        for (int j = 0; j < 8; j++)
#pragma unroll
            for (int r = 0; r < 4; r++) acc[i][j][r] = 0.f;

    const int lrow  = tid >> 2;
    const int lquad = (tid & 3) * 4;
    const float* Ap = A + (size_t)(m0 + lrow) * K + lquad;
    const float* Bp = B + (size_t)(n0 + lrow) * K + lquad;

    float4 a0 = *(const float4*)(Ap);
    float4 a1 = *(const float4*)(Ap + (size_t)64 * K);
    float4 b0 = *(const float4*)(Bp);
    float4 b1 = *(const float4*)(Bp + (size_t)64 * K);

    for (int k0 = 0; k0 < K; k0 += 16) {
        uint32_t* as0 = &As[lrow * GSTR + lquad];
        uint32_t* as1 = &As[(lrow + 64) * GSTR + lquad];
        uint32_t* bs0 = &Bs[lrow * GSTR + lquad];
        uint32_t* bs1 = &Bs[(lrow + 64) * GSTR + lquad];
        as0[0] = f2tf32(a0.x); as0[1] = f2tf32(a0.y); as0[2] = f2tf32(a0.z); as0[3] = f2tf32(a0.w);
        as1[0] = f2tf32(a1.x); as1[1] = f2tf32(a1.y); as1[2] = f2tf32(a1.z); as1[3] = f2tf32(a1.w);
        bs0[0] = f2tf32(b0.x); bs0[1] = f2tf32(b0.y); bs0[2] = f2tf32(b0.z); bs0[3] = f2tf32(b0.w);
        bs1[0] = f2tf32(b1.x); bs1[1] = f2tf32(b1.y); bs1[2] = f2tf32(b1.z); bs1[3] = f2tf32(b1.w);
        __syncthreads();

        // prefetch next chunk while tensor cores work
        if (k0 + 16 < K) {
            a0 = *(const float4*)(Ap + k0 + 16);
            a1 = *(const float4*)(Ap + (size_t)64 * K + k0 + 16);
            b0 = *(const float4*)(Bp + k0 + 16);
            b1 = *(const float4*)(Bp + (size_t)64 * K + k0 + 16);
        }

#pragma unroll
        for (int ks = 0; ks < 16; ks += 8) {
            uint32_t afrag[2][4], bfrag[8][2];
#pragma unroll
            for (int mi = 0; mi < 2; mi++) {
                const int row = wm + mi * 16 + g;
                afrag[mi][0] = As[row * GSTR + ks + tg];
                afrag[mi][1] = As[(row + 8) * GSTR + ks + tg];
                afrag[mi][2] = As[row * GSTR + ks + tg + 4];
                afrag[mi][3] = As[(row + 8) * GSTR + ks + tg + 4];
            }
#pragma unroll
            for (int ni = 0; ni < 8; ni++) {
                const int col = wn + ni * 8 + g;
                bfrag[ni][0] = Bs[col * GSTR + ks + tg];
                bfrag[ni][1] = Bs[col * GSTR + ks + tg + 4];
            }
#pragma unroll
            for (int mi = 0; mi < 2; mi++)
#pragma unroll
                for (int ni = 0; ni < 8; ni++)
                    mma_tf32(acc[mi][ni], afrag[mi], bfrag[ni]);
        }
        __syncthreads();
    }

#pragma unroll
    for (int mi = 0; mi < 2; mi++) {
#pragma unroll
        for (int ni = 0; ni < 8; ni++) {
            const int m = m0 + wm + mi * 16 + g;
            const int n = n0 + wn + ni * 8 + tg * 2;
            const float bx = bias[n], by = bias[n + 1];
            float2 v0 = make_float2(acc[mi][ni][0] + bx, acc[mi][ni][1] + by);
            float2 v1 = make_float2(acc[mi][ni][2] + bx, acc[mi][ni][3] + by);
            if (addend) {
                float2 d0 = *(const float2*)(addend + (size_t)m * N + n);
                float2 d1 = *(const float2*)(addend + (size_t)(m + 8) * N + n);
                v0.x += d0.x; v0.y += d0.y; v1.x += d1.x; v1.y += d1.y;
            }
            *(float2*)(C + (size_t)m * N + n) = v0;
            *(float2*)(C + (size_t)(m + 8) * N + n) = v1;
        }
    }
}

// ---------------------------------------------------------------------------
// Attention pass, 128q x 128k score tiles, 8x8 microtile, transposed smem.
// Phase 1: scores -> g_scores (scaled), running max/sum.
// Phase 2: reread scores, normalize (optionally emit attn), ctx = P V.
// ---------------------------------------------------------------------------
#define QSTR 132   // words; [64 d][128 rows] transposed, mult of 4
#define PSTR 132   // words; [128 q][128 k]
#define VSTR 68    // words; [128 k][64 d]
#define ATTN_SMEM ((128 * PSTR + 128 * VSTR) * 4)   // 102,400 B

__global__ void __launch_bounds__(256, 2)
attn_pass(const float* __restrict__ Qbase, int q_head_stride, int q_row_stride,
          const float* __restrict__ Kin, const float* __restrict__ Vin,
          float* __restrict__ scores,
          float* __restrict__ attn_out,   // nullptr for pass 2
          float* __restrict__ ctx_out, int ctx_off)
{
    extern __shared__ float sm[];
    float* sQT = sm;                 // phase 1: [64][QSTR]
    float* sKT = sm + 64 * QSTR;     // phase 1: [64][QSTR]
    float* sP  = sm;                 // phase 2: [128][PSTR] (aliases sQT+sKT)
    float* sV  = sm + 128 * PSTR;    // phase 2: [128][VSTR]

    const int H   = blockIdx.y;
    const int q0  = blockIdx.x * 128;
    const int tid = threadIdx.x;
    const int tx  = tid & 15, ty = tid >> 4;

    const float* Qh = Qbase + (size_t)H * q_head_stride + (size_t)q0 * q_row_stride;
    const float* Kh = Kin + (size_t)H * (SEQ * DH);
    const float* Vh = Vin + (size_t)H * (SEQ * DH);
    float* Sh = scores + (size_t)H * SEQ * SEQ + (size_t)q0 * SEQ;

    // Load Q tile (128x64) transposed into sQT[d][q]
    {
        const int r  = tid >> 1;            // 0..127
        const int c0 = (tid & 1) * 32;
#pragma unroll
        for (int i = 0; i < 8; i++) {
            float4 v = *(const float4*)(Qh + (size_t)r * q_row_stride + c0 + i * 4);
            sQT[(c0 + i * 4 + 0) * QSTR + r] = v.x;
            sQT[(c0 + i * 4 + 1) * QSTR + r] = v.y;
            sQT[(c0 + i * 4 + 2) * QSTR + r] = v.z;
            sQT[(c0 + i * 4 + 3) * QSTR + r] = v.w;
        }
    }

    float mrow[8], lrow[8];
#pragma unroll
    for (int i = 0; i < 8; i++) { mrow[i] = -INFINITY; lrow[i] = 0.f; }

    __syncthreads();

    // ------------- Phase 1: scores + stats -------------
    for (int kb = 0; kb < 8; kb++) {
        {
            const int r  = tid >> 1;
            const int c0 = (tid & 1) * 32;
#pragma unroll
            for (int i = 0; i < 8; i++) {
                float4 v = *(const float4*)(Kh + (size_t)(kb * 128 + r) * DH + c0 + i * 4);
                sKT[(c0 + i * 4 + 0) * QSTR + r] = v.x;
                sKT[(c0 + i * 4 + 1) * QSTR + r] = v.y;
                sKT[(c0 + i * 4 + 2) * QSTR + r] = v.z;
                sKT[(c0 + i * 4 + 3) * QSTR + r] = v.w;
            }
        }
        __syncthreads();

        float s[8][8];
#pragma unroll
        for (int a = 0; a < 8; a++)
#pragma unroll
            for (int b = 0; b < 8; b++) s[a][b] = 0.f;

#pragma unroll 8
        for (int d = 0; d < 64; d++) {
            float4 qa0 = *(const float4*)&sQT[d * QSTR + ty * 8];
            float4 qa1 = *(const float4*)&sQT[d * QSTR + ty * 8 + 4];
            float4 kb0 = *(const float4*)&sKT[d * QSTR + tx * 8];
            float4 kb1 = *(const float4*)&sKT[d * QSTR + tx * 8 + 4];
            const float qa[8] = {qa0.x, qa0.y, qa0.z, qa0.w, qa1.x, qa1.y, qa1.z, qa1.w};
            const float kv[8] = {kb0.x, kb0.y, kb0.z, kb0.w, kb1.x, kb1.y, kb1.z, kb1.w};
#pragma unroll
            for (int a = 0; a < 8; a++)
#pragma unroll
                for (int b = 0; b < 8; b++)
                    s[a][b] = fmaf(qa[a], kv[b], s[a][b]);
        }

#pragma unroll
        for (int a = 0; a < 8; a++) {
#pragma unroll
            for (int b = 0; b < 8; b++) s[a][b] *= 8.f;   // scale = sqrt(d_head)
            // cache scaled scores
            float* dst = Sh + (size_t)(ty * 8 + a) * SEQ + kb * 128 + tx * 8;
            *(float4*)(dst)     = make_float4(s[a][0], s[a][1], s[a][2], s[a][3]);
            *(float4*)(dst + 4) = make_float4(s[a][4], s[a][5], s[a][6], s[a][7]);
            float mx = s[a][0];
#pragma unroll
            for (int b = 1; b < 8; b++) mx = fmaxf(mx, s[a][b]);
#pragma unroll
            for (int off = 8; off; off >>= 1)
                mx = fmaxf(mx, __shfl_xor_sync(0xffffffffu, mx, off));
            const float nm = fmaxf(mrow[a], mx);
            float se = 0.f;
#pragma unroll
            for (int b = 0; b < 8; b++) se += __expf(s[a][b] - nm);
#pragma unroll
            for (int off = 8; off; off >>= 1)
                se += __shfl_xor_sync(0xffffffffu, se, off);
            lrow[a] = lrow[a] * __expf(mrow[a] - nm) + se;
            mrow[a] = nm;
        }
        __syncthreads();
    }

    float invl[8];
#pragma unroll
    for (int a = 0; a < 8; a++) invl[a] = 1.f / lrow[a];

    float ctx[8][4];
#pragma unroll
    for (int a = 0; a < 8; a++)
#pragma unroll
        for (int b = 0; b < 4; b++) ctx[a][b] = 0.f;

    // ------------- Phase 2: normalize + PV -------------
    for (int kb = 0; kb < 8; kb++) {
        {
            const int r  = tid >> 1;
            const int c0 = (tid & 1) * 32;
#pragma unroll
            for (int i = 0; i < 8; i++) {
                float4 v = *(const float4*)(Vh + (size_t)(kb * 128 + r) * DH + c0 + i * 4);
                *(float4*)&sV[r * VSTR + c0 + i * 4] = v;
            }
        }
#pragma unroll
        for (int a = 0; a < 8; a++) {
            const float* src = Sh + (size_t)(ty * 8 + a) * SEQ + kb * 128 + tx * 8;
            float4 s0 = *(const float4*)(src);
            float4 s1 = *(const float4*)(src + 4);
            float4 p0, p1;
            p0.x = __expf(s0.x - mrow[a]) * invl[a];
            p0.y = __expf(s0.y - mrow[a]) * invl[a];
            p0.z = __expf(s0.z - mrow[a]) * invl[a];
            p0.w = __expf(s0.w - mrow[a]) * invl[a];
            p1.x = __expf(s1.x - mrow[a]) * invl[a];
            p1.y = __expf(s1.y - mrow[a]) * invl[a];
            p1.z = __expf(s1.z - mrow[a]) * invl[a];
            p1.w = __expf(s1.w - mrow[a]) * invl[a];
            *(float4*)&sP[(ty * 8 + a) * PSTR + tx * 8]     = p0;
            *(float4*)&sP[(ty * 8 + a) * PSTR + tx * 8 + 4] = p1;
            if (attn_out) {
                float* dst = attn_out + ((size_t)H * SEQ + q0 + ty * 8 + a) * SEQ + kb * 128 + tx * 8;
                *(float4*)(dst)     = p0;
                *(float4*)(dst + 4) = p1;
            }
        }
        __syncthreads();

#pragma unroll 4
        for (int k = 0; k < 128; k++) {
            float4 v4 = *(const float4*)&sV[k * VSTR + tx * 4];
#pragma unroll
            for (int a = 0; a < 8; a++) {
                const float p = sP[(ty * 8 + a) * PSTR + k];
                ctx[a][0] = fmaf(p, v4.x, ctx[a][0]);
                ctx[a][1] = fmaf(p, v4.y, ctx[a][1]);
                ctx[a][2] = fmaf(p, v4.z, ctx[a][2]);
                ctx[a][3] = fmaf(p, v4.w, ctx[a][3]);
            }
        }
        __syncthreads();
    }

    // Write ctx into interleaved ctot (row stride 128) at ctx_off
#pragma unroll
    for (int a = 0; a < 8; a++) {
        float* dst = ctx_out + ((size_t)H * SEQ + q0 + ty * 8 + a) * 128 + ctx_off + tx * 4;
        *(float4*)dst = make_float4(ctx[a][0], ctx[a][1], ctx[a][2], ctx[a][3]);
    }
}

// ---------------------------------------------------------------------------
// Row LayerNorm over ND=2048
// ---------------------------------------------------------------------------
__global__ void ln_kernel(const float* __restrict__ X, const float* __restrict__ gamma,
                          const float* __restrict__ beta, float* __restrict__ Y)
{
    __shared__ float red[64];
    const int row = blockIdx.x;
    const float* x = X + (size_t)row * ND;
    float sum = 0.f, sq = 0.f;
    for (int i = threadIdx.x; i < ND; i += blockDim.x) {
        const float v = x[i];
        sum += v; sq += v * v;
    }
#pragma unroll
    for (int off = 16; off; off >>= 1) {
        sum += __shfl_xor_sync(0xffffffffu, sum, off);
        sq  += __shfl_xor_sync(0xffffffffu, sq, off);
    }
    const int warp = threadIdx.x >> 5, lane = threadIdx.x & 31;
    if (lane == 0) { red[warp] = sum; red[warp + 32] = sq; }
    __syncthreads();
    if (warp == 0) {
        sum = (lane < 8) ? red[lane] : 0.f;
        sq  = (lane < 8) ? red[lane + 32] : 0.f;
#pragma unroll
        for (int off = 4; off; off >>= 1) {
            sum += __shfl_xor_sync(0xffffffffu, sum, off);
            sq  += __shfl_xor_sync(0xffffffffu, sq, off);
        }
        if (lane == 0) { red[0] = sum; red[1] = sq; }
    }
    __syncthreads();
    const float mu  = red[0] * (1.f / ND);
    const float var = red[1] * (1.f / ND) - mu * mu;
    const float inv = rsqrtf(var + 1e-5f);
    float* y = Y + (size_t)row * ND;
    for (int i = threadIdx.x; i < ND; i += blockDim.x)
        y[i] = (x[i] - mu) * inv * gamma[i] + beta[i];
}

// ---------------------------------------------------------------------------
extern "C" void kernel_launch(void* const* d_in, const int* in_sizes, int n_in,
                              void* d_out, int out_size)
{
    const float* k_in  = (const float*)d_in[0];
    const float* v_in  = (const float*)d_in[1];
    const float* q_in  = (const float*)d_in[2];
    const float* r_in  = (const float*)d_in[3];
    const float* Wr    = (const float*)d_in[4];
    const float* br    = (const float*)d_in[5];
    const float* Wf    = (const float*)d_in[6];
    const float* bf    = (const float*)d_in[7];
    const float* gamma = (const float*)d_in[8];
    const float* beta  = (const float*)d_in[9];

    float* out      = (float*)d_out;
    float* y_out    = out;
    float* attn_out = out + (size_t)MROWS * ND;

    float* rp;     cudaGetSymbolAddress((void**)&rp, g_rp);
    float* ctot;   cudaGetSymbolAddress((void**)&ctot, g_ctot);
    float* scores; cudaGetSymbolAddress((void**)&scores, g_scores);

    cudaFuncSetAttribute(attn_pass, cudaFuncAttributeMaxDynamicSharedMemorySize, ATTN_SMEM);

    // 1) rp = r @ Wr^T + br
    dim3 g1(ND / 128, MROWS / 128);
    gemm_tf32<<<g1, 256>>>(r_in, Wr, br, nullptr, rp, MROWS, ND, MD);

    // 2) pass 1: attn1 -> d_out, ctx1 -> ctot[..,0:64]
    dim3 ga(SEQ / 128, HEADS);
    attn_pass<<<ga, 256, ATTN_SMEM>>>(q_in, SEQ * DH, DH, k_in, v_in, scores, attn_out, ctot, 0);

    // 3) pass 2: queries = ctx1, ctx2 -> ctot[..,64:128]
    attn_pass<<<ga, 256, ATTN_SMEM>>>(ctot, SEQ * 128, 128, k_in, v_in, scores, nullptr, ctot, 64);

    // 4) x = ctot @ Wf^T + bf + rp
    gemm_tf32<<<g1, 256>>>(ctot, Wf, bf, rp, rp, MROWS, ND, ND);

    // 5) y = LayerNorm(x)
    ln_kernel<<<MROWS, 256>>>(rp, gamma, beta, y_out);
}

// round 6
// speedup vs baseline: 1.9354x; 1.1082x over previous
#include <cuda_runtime.h>
#include <cstdint>
#include <math.h>

// Problem dims (fixed)
#define SEQ   1024
#define DH    64
#define HEADS 64          // bz*16
#define MD    1024        // model_dim
#define ND    2048        // model_dim * n_scale
#define MROWS 4096        // bz*seq

// Scratch (allocation-free rule: device globals)
__device__ float g_rp[(size_t)MROWS * ND];            // 32 MB
__device__ float g_ctot[(size_t)HEADS * SEQ * 128];   // 32 MB: ctx1/ctx2 interleaved
__device__ float g_scores[(size_t)HEADS * SEQ * SEQ]; // 256 MB: raw scaled scores

// ---------------------------------------------------------------------------
// Common MMA helpers
// ---------------------------------------------------------------------------
__device__ __forceinline__ uint32_t f2tf32(float x) {
    uint32_t r;
    asm("cvt.rna.tf32.f32 %0, %1;" : "=r"(r) : "f"(x));
    return r;
}

// split x into tf32 hi + tf32 lo (x ~= hi + lo, |lo| <= 2^-11 |x|)
__device__ __forceinline__ void hilo(float x, uint32_t& h, uint32_t& l) {
    h = f2tf32(x);
    l = f2tf32(x - __uint_as_float(h));
}

__device__ __forceinline__ void mma_tf32(float* c, const uint32_t* a, const uint32_t* b) {
    asm volatile(
        "mma.sync.aligned.m16n8k8.row.col.f32.tf32.tf32.f32 "
        "{%0,%1,%2,%3},{%4,%5,%6,%7},{%8,%9},{%0,%1,%2,%3};"
        : "+f"(c[0]), "+f"(c[1]), "+f"(c[2]), "+f"(c[3])
        : "r"(a[0]), "r"(a[1]), "r"(a[2]), "r"(a[3]), "r"(b[0]), "r"(b[1]));
}

__device__ __forceinline__ void cp16(void* smem, const void* gmem) {
    uint32_t s = (uint32_t)__cvta_generic_to_shared(smem);
    asm volatile("cp.async.ca.shared.global [%0], [%1], 16;" :: "r"(s), "l"(gmem));
}
#define CP_COMMIT() asm volatile("cp.async.commit_group;")
#define CP_WAIT1()  asm volatile("cp.async.wait_group 1;")
#define CP_WAIT0()  asm volatile("cp.async.wait_group 0;")

// ---------------------------------------------------------------------------
// TF32 GEMM, cp.async 2-stage double buffer: C = A B^T + bias (+ addend)
// BM=BN=128, BK=16, 256 threads, warp tile 32x64.
// ---------------------------------------------------------------------------
#define GSTR 20

__global__ void __launch_bounds__(256) gemm_tf32(
    const float* __restrict__ A, const float* __restrict__ B,
    const float* __restrict__ bias, const float* __restrict__ addend,
    float* __restrict__ C, int M, int N, int K)
{
    __shared__ float As[2][128 * GSTR];
    __shared__ float Bs[2][128 * GSTR];

    const int tid  = threadIdx.x;
    const int warp = tid >> 5, lane = tid & 31;
    const int wm = (warp >> 1) * 32;
    const int wn = (warp & 1) * 64;
    const int m0 = blockIdx.y * 128, n0 = blockIdx.x * 128;
    const int g  = lane >> 2;
    const int tg = lane & 3;

    float acc[2][8][4];
#pragma unroll
    for (int i = 0; i < 2; i++)
#pragma unroll
        for (int j = 0; j < 8; j++)
#pragma unroll
            for (int r = 0; r < 4; r++) acc[i][j][r] = 0.f;

    // cp.async loader: 512 float4 per tile per matrix, 2 per thread each
    const int r0 = tid >> 1;                 // via idx decomposition below
    (void)r0;

    auto load_stage = [&](int s, int k0) {
#pragma unroll
        for (int i = 0; i < 2; i++) {
            const int idx = tid + 256 * i;
            const int row = idx >> 2;
            const int cq  = (idx & 3) * 4;
            cp16(&As[s][row * GSTR + cq], A + (size_t)(m0 + row) * K + k0 + cq);
            cp16(&Bs[s][row * GSTR + cq], B + (size_t)(n0 + row) * K + k0 + cq);
        }
    };

    const int ntiles = K / 16;
    load_stage(0, 0);
    CP_COMMIT();

    for (int t = 0; t < ntiles; t++) {
        if (t + 1 < ntiles) {
            load_stage((t + 1) & 1, (t + 1) * 16);
            CP_COMMIT();
            CP_WAIT1();
        } else {
            CP_WAIT0();
        }
        __syncthreads();

        const float* Ab = As[t & 1];
        const float* Bb = Bs[t & 1];
#pragma unroll
        for (int ks = 0; ks < 16; ks += 8) {
            uint32_t afrag[2][4], bfrag[8][2];
#pragma unroll
            for (int mi = 0; mi < 2; mi++) {
                const int row = wm + mi * 16 + g;
                afrag[mi][0] = f2tf32(Ab[row * GSTR + ks + tg]);
                afrag[mi][1] = f2tf32(Ab[(row + 8) * GSTR + ks + tg]);
                afrag[mi][2] = f2tf32(Ab[row * GSTR + ks + tg + 4]);
                afrag[mi][3] = f2tf32(Ab[(row + 8) * GSTR + ks + tg + 4]);
            }
#pragma unroll
            for (int ni = 0; ni < 8; ni++) {
                const int col = wn + ni * 8 + g;
                bfrag[ni][0] = f2tf32(Bb[col * GSTR + ks + tg]);
                bfrag[ni][1] = f2tf32(Bb[col * GSTR + ks + tg + 4]);
            }
#pragma unroll
            for (int mi = 0; mi < 2; mi++)
#pragma unroll
                for (int ni = 0; ni < 8; ni++)
                    mma_tf32(acc[mi][ni], afrag[mi], bfrag[ni]);
        }
        __syncthreads();
    }

#pragma unroll
    for (int mi = 0; mi < 2; mi++) {
#pragma unroll
        for (int ni = 0; ni < 8; ni++) {
            const int m = m0 + wm + mi * 16 + g;
            const int n = n0 + wn + ni * 8 + tg * 2;
            const float bx = bias[n], by = bias[n + 1];
            float2 v0 = make_float2(acc[mi][ni][0] + bx, acc[mi][ni][1] + by);
            float2 v1 = make_float2(acc[mi][ni][2] + bx, acc[mi][ni][3] + by);
            if (addend) {
                float2 d0 = *(const float2*)(addend + (size_t)m * N + n);
                float2 d1 = *(const float2*)(addend + (size_t)(m + 8) * N + n);
                v0.x += d0.x; v0.y += d0.y; v1.x += d1.x; v1.y += d1.y;
            }
            *(float2*)(C + (size_t)m * N + n) = v0;
            *(float2*)(C + (size_t)(m + 8) * N + n) = v1;
        }
    }
}

// ---------------------------------------------------------------------------
// Tensor-core attention (tf32x3 = fp32-equivalent precision).
// Block: 128 q rows x one head; 8 warps, warp w owns q rows [16w,16w+16).
// Phase 1: scores = 8*(Q K^T) via mma tf32x3 -> g_scores + streaming (m,l).
// Phase 2: p = exp(s-m)/l from cached scores (read at A-frag positions),
//          optional attn output, ctx = P V via mma tf32x3.
// ---------------------------------------------------------------------------
#define ASTR 68
#define ATTN_SMEM (2 * 128 * ASTR * 4)   // 69,632 B

__global__ void __launch_bounds__(256, 2)
attn_mma(const float* __restrict__ Qbase, int q_head_stride, int q_row_stride,
         const float* __restrict__ Kin, const float* __restrict__ Vin,
         float* __restrict__ scores,
         float* __restrict__ attn_out,   // nullptr for pass 2
         float* __restrict__ ctx_out, int ctx_off)
{
    extern __shared__ float smf[];
    float* sQ  = smf;                // [128][ASTR]
    float* sKV = smf + 128 * ASTR;   // [128][ASTR]  (K in phase 1, V in phase 2)

    const int H   = blockIdx.y;
    const int q0  = blockIdx.x * 128;
    const int tid = threadIdx.x;
    const int w   = tid >> 5, lane = tid & 31;
    const int g   = lane >> 2, tg = lane & 3;
    const int wq  = w * 16;

    const float* Qh = Qbase + (size_t)H * q_head_stride + (size_t)q0 * q_row_stride;
    const float* Kh = Kin + (size_t)H * (SEQ * DH);
    const float* Vh = Vin + (size_t)H * (SEQ * DH);
    float* Sh = scores + (size_t)H * SEQ * SEQ + (size_t)q0 * SEQ;

    // ---- load Q tile (128x64) into smem, coalesced ----
    {
        const int r  = tid >> 1;
        const int c0 = (tid & 1) * 32;
#pragma unroll
        for (int i = 0; i < 8; i++) {
            float4 v = *(const float4*)(Qh + (size_t)r * q_row_stride + c0 + i * 4);
            *(float4*)&sQ[r * ASTR + c0 + i * 4] = v;
        }
    }
    __syncthreads();

    // ---- extract warp's Q fragments (rows wq+g, wq+g+8), hi/lo split ----
    uint32_t qh[8][4], ql[8][4];
#pragma unroll
    for (int kc = 0; kc < 8; kc++) {
        const int col = 8 * kc + tg;
        hilo(sQ[(wq + g) * ASTR + col],         qh[kc][0], ql[kc][0]);
        hilo(sQ[(wq + g + 8) * ASTR + col],     qh[kc][1], ql[kc][1]);
        hilo(sQ[(wq + g) * ASTR + col + 4],     qh[kc][2], ql[kc][2]);
        hilo(sQ[(wq + g + 8) * ASTR + col + 4], qh[kc][3], ql[kc][3]);
    }

    float mloc[2] = {-INFINITY, -INFINITY};
    float lloc[2] = {0.f, 0.f};

    // ================= Phase 1: scores + streaming stats =================
    for (int kb = 0; kb < 8; kb++) {
        __syncthreads();
        {
            const int r  = tid >> 1;
            const int c0 = (tid & 1) * 32;
#pragma unroll
            for (int i = 0; i < 8; i++) {
                float4 v = *(const float4*)(Kh + (size_t)(kb * 128 + r) * DH + c0 + i * 4);
                *(float4*)&sKV[r * ASTR + c0 + i * 4] = v;
            }
        }
        __syncthreads();

#pragma unroll 1
        for (int nt = 0; nt < 16; nt++) {
            float acc[4] = {0.f, 0.f, 0.f, 0.f};
#pragma unroll
            for (int kc = 0; kc < 8; kc++) {
                uint32_t bh[2], bl[2];
                hilo(sKV[(8 * nt + g) * ASTR + 8 * kc + tg],     bh[0], bl[0]);
                hilo(sKV[(8 * nt + g) * ASTR + 8 * kc + tg + 4], bh[1], bl[1]);
                mma_tf32(acc, qh[kc], bh);
                mma_tf32(acc, qh[kc], bl);
                mma_tf32(acc, ql[kc], bh);
            }
#pragma unroll
            for (int j = 0; j < 4; j++) acc[j] *= 8.f;   // scale = sqrt(d_head)

            // cache scaled scores (c-layout: rows g,g+8; cols 8nt+2tg,+1)
            *(float2*)(Sh + (size_t)(wq + g) * SEQ + kb * 128 + 8 * nt + 2 * tg)
                = make_float2(acc[0], acc[1]);
            *(float2*)(Sh + (size_t)(wq + g + 8) * SEQ + kb * 128 + 8 * nt + 2 * tg)
                = make_float2(acc[2], acc[3]);

            // streaming per-thread (m,l) update, rows 0 (g) and 1 (g+8)
            {
                const float mx = fmaxf(acc[0], acc[1]);
                const float nm = fmaxf(mloc[0], mx);
                lloc[0] = lloc[0] * __expf(mloc[0] - nm) + __expf(acc[0] - nm) + __expf(acc[1] - nm);
                mloc[0] = nm;
            }
            {
                const float mx = fmaxf(acc[2], acc[3]);
                const float nm = fmaxf(mloc[1], mx);
                lloc[1] = lloc[1] * __expf(mloc[1] - nm) + __expf(acc[2] - nm) + __expf(acc[3] - nm);
                mloc[1] = nm;
            }
        }
    }

    // ---- merge (m,l) across the quad (4 threads share each row) ----
    float invl[2];
#pragma unroll
    for (int i = 0; i < 2; i++) {
#pragma unroll
        for (int off = 1; off <= 2; off <<= 1) {
            const float om = __shfl_xor_sync(0xffffffffu, mloc[i], off);
            const float ol = __shfl_xor_sync(0xffffffffu, lloc[i], off);
            const float nm = fmaxf(mloc[i], om);
            lloc[i] = lloc[i] * __expf(mloc[i] - nm) + ol * __expf(om - nm);
            mloc[i] = nm;
        }
        invl[i] = 1.f / lloc[i];
    }

    // ================= Phase 2: probabilities + PV =================
    float ctx[8][4];
#pragma unroll
    for (int nt = 0; nt < 8; nt++)
#pragma unroll
        for (int j = 0; j < 4; j++) ctx[nt][j] = 0.f;

    for (int kb = 0; kb < 8; kb++) {
        __syncthreads();
        {
            const int r  = tid >> 1;
            const int c0 = (tid & 1) * 32;
#pragma unroll
            for (int i = 0; i < 8; i++) {
                float4 v = *(const float4*)(Vh + (size_t)(kb * 128 + r) * DH + c0 + i * 4);
                *(float4*)&sKV[r * ASTR + c0 + i * 4] = v;
            }
        }
        __syncthreads();

#pragma unroll 1
        for (int kc = 0; kc < 16; kc++) {
            const int cbase = kb * 128 + 8 * kc;
            // read scores at A-fragment positions
            const float s0 = Sh[(size_t)(wq + g) * SEQ + cbase + tg];
            const float s1 = Sh[(size_t)(wq + g + 8) * SEQ + cbase + tg];
            const float s2 = Sh[(size_t)(wq + g) * SEQ + cbase + tg + 4];
            const float s3 = Sh[(size_t)(wq + g + 8) * SEQ + cbase + tg + 4];
            const float p0 = __expf(s0 - mloc[0]) * invl[0];
            const float p1 = __expf(s1 - mloc[1]) * invl[1];
            const float p2 = __expf(s2 - mloc[0]) * invl[0];
            const float p3 = __expf(s3 - mloc[1]) * invl[1];

            if (attn_out) {
                float* ao = attn_out + ((size_t)H * SEQ + q0) * SEQ;
                ao[(size_t)(wq + g) * SEQ + cbase + tg]         = p0;
                ao[(size_t)(wq + g + 8) * SEQ + cbase + tg]     = p1;
                ao[(size_t)(wq + g) * SEQ + cbase + tg + 4]     = p2;
                ao[(size_t)(wq + g + 8) * SEQ + cbase + tg + 4] = p3;
            }

            uint32_t ph[4], pl[4];
            hilo(p0, ph[0], pl[0]);
            hilo(p1, ph[1], pl[1]);
            hilo(p2, ph[2], pl[2]);
            hilo(p3, ph[3], pl[3]);

#pragma unroll
            for (int nt = 0; nt < 8; nt++) {
                uint32_t vh[2], vl[2];
                hilo(sKV[(8 * kc + tg) * ASTR + 8 * nt + g],     vh[0], vl[0]);
                hilo(sKV[(8 * kc + tg + 4) * ASTR + 8 * nt + g], vh[1], vl[1]);
                mma_tf32(ctx[nt], ph, vh);
                mma_tf32(ctx[nt], ph, vl);
                mma_tf32(ctx[nt], pl, vh);
            }
        }
    }

    // ---- write ctx into interleaved ctot (row stride 128) ----
#pragma unroll
    for (int nt = 0; nt < 8; nt++) {
        const int c = ctx_off + 8 * nt + 2 * tg;
        *(float2*)(ctx_out + ((size_t)H * SEQ + q0 + wq + g) * 128 + c)
            = make_float2(ctx[nt][0], ctx[nt][1]);
        *(float2*)(ctx_out + ((size_t)H * SEQ + q0 + wq + g + 8) * 128 + c)
            = make_float2(ctx[nt][2], ctx[nt][3]);
    }
}

// ---------------------------------------------------------------------------
// Row LayerNorm over ND=2048
// ---------------------------------------------------------------------------
__global__ void ln_kernel(const float* __restrict__ X, const float* __restrict__ gamma,
                          const float* __restrict__ beta, float* __restrict__ Y)
{
    __shared__ float red[64];
    const int row = blockIdx.x;
    const float* x = X + (size_t)row * ND;
    float sum = 0.f, sq = 0.f;
    for (int i = threadIdx.x; i < ND; i += blockDim.x) {
        const float v = x[i];
        sum += v; sq += v * v;
    }
#pragma unroll
    for (int off = 16; off; off >>= 1) {
        sum += __shfl_xor_sync(0xffffffffu, sum, off);
        sq  += __shfl_xor_sync(0xffffffffu, sq, off);
    }
    const int warp = threadIdx.x >> 5, lane = threadIdx.x & 31;
    if (lane == 0) { red[warp] = sum; red[warp + 32] = sq; }
    __syncthreads();
    if (warp == 0) {
        sum = (lane < 8) ? red[lane] : 0.f;
        sq  = (lane < 8) ? red[lane + 32] : 0.f;
#pragma unroll
        for (int off = 4; off; off >>= 1) {
            sum += __shfl_xor_sync(0xffffffffu, sum, off);
            sq  += __shfl_xor_sync(0xffffffffu, sq, off);
        }
        if (lane == 0) { red[0] = sum; red[1] = sq; }
    }
    __syncthreads();
    const float mu  = red[0] * (1.f / ND);
    const float var = red[1] * (1.f / ND) - mu * mu;
    const float inv = rsqrtf(var + 1e-5f);
    float* y = Y + (size_t)row * ND;
    for (int i = threadIdx.x; i < ND; i += blockDim.x)
        y[i] = (x[i] - mu) * inv * gamma[i] + beta[i];
}

// ---------------------------------------------------------------------------
extern "C" void kernel_launch(void* const* d_in, const int* in_sizes, int n_in,
                              void* d_out, int out_size)
{
    const float* k_in  = (const float*)d_in[0];
    const float* v_in  = (const float*)d_in[1];
    const float* q_in  = (const float*)d_in[2];
    const float* r_in  = (const float*)d_in[3];
    const float* Wr    = (const float*)d_in[4];
    const float* br    = (const float*)d_in[5];
    const float* Wf    = (const float*)d_in[6];
    const float* bf    = (const float*)d_in[7];
    const float* gamma = (const float*)d_in[8];
    const float* beta  = (const float*)d_in[9];

    float* out      = (float*)d_out;
    float* y_out    = out;
    float* attn_out = out + (size_t)MROWS * ND;

    float* rp;     cudaGetSymbolAddress((void**)&rp, g_rp);
    float* ctot;   cudaGetSymbolAddress((void**)&ctot, g_ctot);
    float* scores; cudaGetSymbolAddress((void**)&scores, g_scores);

    cudaFuncSetAttribute(attn_mma, cudaFuncAttributeMaxDynamicSharedMemorySize, ATTN_SMEM);

    // 1) rp = r @ Wr^T + br
    dim3 g1(ND / 128, MROWS / 128);
    gemm_tf32<<<g1, 256>>>(r_in, Wr, br, nullptr, rp, MROWS, ND, MD);

    // 2) pass 1: attn1 -> d_out, ctx1 -> ctot[..,0:64]
    dim3 ga(SEQ / 128, HEADS);
    attn_mma<<<ga, 256, ATTN_SMEM>>>(q_in, SEQ * DH, DH, k_in, v_in, scores, attn_out, ctot, 0);

    // 3) pass 2: queries = ctx1 (stride 128), ctx2 -> ctot[..,64:128]
    attn_mma<<<ga, 256, ATTN_SMEM>>>(ctot, SEQ * 128, 128, k_in, v_in, scores, nullptr, ctot, 64);

    // 4) x = ctot @ Wf^T + bf + rp
    gemm_tf32<<<g1, 256>>>(ctot, Wf, bf, rp, rp, MROWS, ND, ND);

    // 5) y = LayerNorm(x)
    ln_kernel<<<MROWS, 256>>>(rp, gamma, beta, y_out);
}